// round 2
// baseline (speedup 1.0000x reference)
#include <cuda_runtime.h>
#include <cuda_bf16.h>
#include <math.h>

#define N_NODES 50000
#define N_EDGES 800000
#define HDIM    128
#define NLAYERS 3
#define NGRAPHS 64
#define BN_EPS  1e-5f

// ---------------- scratch (device globals: no runtime allocation) ----------
// __align__(16): these are accessed via float4 (incl. vector atomics).
__device__ __align__(16) float g_agg [N_NODES * HDIM];
__device__ __align__(16) float g_buf0[N_NODES * HDIM];
__device__ __align__(16) float g_buf1[N_NODES * HDIM];
__device__ float g_deg   [N_NODES];
__device__ float g_invdeg[N_NODES];
__device__ __align__(16) float g_affa[HDIM];
__device__ __align__(16) float g_affb[HDIM];
__device__ float g_colsum[HDIM];
__device__ float g_colsq [HDIM];
__device__ float g_pool[NGRAPHS];

// ---------------- degree (dst only; same for all layers) -------------------
__global__ void deg_kernel(const int* __restrict__ ei) {
    int e = blockIdx.x * blockDim.x + threadIdx.x;
    if (e < N_EDGES) atomicAdd(&g_deg[ei[N_EDGES + e]], 1.0f);
}

// invdeg + affine init (identity) + zero stats/pool
__global__ void init_kernel() {
    int i = blockIdx.x * blockDim.x + threadIdx.x;
    if (i < N_NODES) g_invdeg[i] = 1.0f / fmaxf(g_deg[i], 1.0f);
    if (i < HDIM) {
        g_affa[i] = 1.0f; g_affb[i] = 0.0f;
        g_colsum[i] = 0.0f; g_colsq[i] = 0.0f;
    }
    if (i < NGRAPHS) g_pool[i] = 0.0f;
}

// ---------------- scatter: agg[dst] += affine(h[src]) ----------------------
// one warp per edge; lane handles a 4-float chunk; vector atomics (sm_90+)
__global__ void scatter_kernel(const float* __restrict__ h,
                               const int* __restrict__ ei) {
    int gt   = blockIdx.x * blockDim.x + threadIdx.x;
    int e    = gt >> 5;
    int lane = gt & 31;
    if (e >= N_EDGES) return;
    int src = ei[e];
    int dst = ei[N_EDGES + e];
    float4 v = ((const float4*)h)[src * 32 + lane];
    float4 a = ((const float4*)g_affa)[lane];
    float4 b = ((const float4*)g_affb)[lane];
    v.x = fmaf(v.x, a.x, b.x);
    v.y = fmaf(v.y, a.y, b.y);
    v.z = fmaf(v.z, a.z, b.z);
    v.w = fmaf(v.w, a.w, b.w);
    atomicAdd(((float4*)g_agg) + dst * 32 + lane, v);
}

// ---------------- fused dual GEMM + bias + relu + BN stats ------------------
// y[i,:] = relu( (agg[i,:]*invdeg[i]) @ Wl^T + affine(hprev[i,:]) @ Wr^T + bias )
// tile: 64 rows x 128 cols per block, 256 threads, K = 256 (128 agg + 128 hprev)
__global__ void __launch_bounds__(256)
gemm_kernel(const float* __restrict__ hprev,
            const float* __restrict__ Wl,
            const float* __restrict__ Wr,
            const float* __restrict__ bias,
            float* __restrict__ yout) {
    __shared__ __align__(16) float As[64 * 32];
    __shared__ __align__(16) float Bs[32 * 132];   // padded
    __shared__ float s_cs[HDIM];
    __shared__ float s_sq[HDIM];

    const int tid  = threadIdx.x;
    const int ty   = tid >> 5;       // 0..7  (8 rows each)
    const int tx   = tid & 31;       // 0..31 (4 cols each)
    const int row0 = blockIdx.x * 64;

    float acc[8][4];
#pragma unroll
    for (int i = 0; i < 8; ++i)
#pragma unroll
        for (int j = 0; j < 4; ++j) acc[i][j] = 0.0f;

#pragma unroll 1
    for (int t = 0; t < 8; ++t) {
        const int  kk     = t * 32;
        const bool second = (kk >= 128);
        const int  kloc   = second ? kk - 128 : kk;
        const float* A = second ? hprev : g_agg;
        const float* W = second ? Wr : Wl;

        // --- load A tile (64 x 32) with on-the-fly transform ---
#pragma unroll
        for (int i = 0; i < 2; ++i) {
            int f  = tid + 256 * i;        // 0..511
            int r  = f >> 3;               // 0..63
            int c4 = f & 7;                // float4 index within 32-wide K slab
            int grow = row0 + r;
            float4 v = make_float4(0.f, 0.f, 0.f, 0.f);
            if (grow < N_NODES) {
                v = *((const float4*)(A + (size_t)grow * HDIM + kloc + c4 * 4));
                if (second) {
                    float4 a = ((const float4*)g_affa)[(kloc >> 2) + c4];
                    float4 b = ((const float4*)g_affb)[(kloc >> 2) + c4];
                    v.x = fmaf(v.x, a.x, b.x);
                    v.y = fmaf(v.y, a.y, b.y);
                    v.z = fmaf(v.z, a.z, b.z);
                    v.w = fmaf(v.w, a.w, b.w);
                } else {
                    float d = g_invdeg[grow];
                    v.x *= d; v.y *= d; v.z *= d; v.w *= d;
                }
            }
            *((float4*)(As + r * 32 + c4 * 4)) = v;
        }
        // --- load B tile (32 x 128), transposed into smem ---
#pragma unroll
        for (int i = 0; i < 4; ++i) {
            int f  = tid + 256 * i;        // 0..1023
            int j  = f >> 3;               // 0..127 output col
            int kq = f & 7;                // float4 index within 32-wide K slab
            float4 w = *((const float4*)(W + (size_t)j * HDIM + kloc + kq * 4));
            Bs[(kq * 4 + 0) * 132 + j] = w.x;
            Bs[(kq * 4 + 1) * 132 + j] = w.y;
            Bs[(kq * 4 + 2) * 132 + j] = w.z;
            Bs[(kq * 4 + 3) * 132 + j] = w.w;
        }
        __syncthreads();

#pragma unroll
        for (int k = 0; k < 32; ++k) {
            float4 bv = *((const float4*)(Bs + k * 132 + tx * 4));
#pragma unroll
            for (int i = 0; i < 8; ++i) {
                float a = As[(ty * 8 + i) * 32 + k];
                acc[i][0] = fmaf(a, bv.x, acc[i][0]);
                acc[i][1] = fmaf(a, bv.y, acc[i][1]);
                acc[i][2] = fmaf(a, bv.z, acc[i][2]);
                acc[i][3] = fmaf(a, bv.w, acc[i][3]);
            }
        }
        __syncthreads();
    }

    // --- epilogue: bias, relu, store, BN stats ---
    const int col = tx * 4;
    float4 bi = *((const float4*)(bias + col));
    float cs[4] = {0.f, 0.f, 0.f, 0.f};
    float sq[4] = {0.f, 0.f, 0.f, 0.f};
#pragma unroll
    for (int i = 0; i < 8; ++i) {
        int grow = row0 + ty * 8 + i;
        if (grow < N_NODES) {
            float4 r;
            r.x = fmaxf(acc[i][0] + bi.x, 0.f);
            r.y = fmaxf(acc[i][1] + bi.y, 0.f);
            r.z = fmaxf(acc[i][2] + bi.z, 0.f);
            r.w = fmaxf(acc[i][3] + bi.w, 0.f);
            *((float4*)(yout + (size_t)grow * HDIM + col)) = r;
            cs[0] += r.x; sq[0] += r.x * r.x;
            cs[1] += r.y; sq[1] += r.y * r.y;
            cs[2] += r.z; sq[2] += r.z * r.z;
            cs[3] += r.w; sq[3] += r.w * r.w;
        }
    }
    if (tid < HDIM) { s_cs[tid] = 0.f; s_sq[tid] = 0.f; }
    __syncthreads();
#pragma unroll
    for (int j = 0; j < 4; ++j) {
        atomicAdd(&s_cs[col + j], cs[j]);
        atomicAdd(&s_sq[col + j], sq[j]);
    }
    __syncthreads();
    if (tid < HDIM) {
        atomicAdd(&g_colsum[tid], s_cs[tid]);
        atomicAdd(&g_colsq [tid], s_sq[tid]);
    }
}

// ---------------- BN finalize -> affine for next consumer ------------------
__global__ void finalize_kernel(const float* __restrict__ gamma,
                                const float* __restrict__ beta) {
    int j = threadIdx.x;
    if (j >= HDIM) return;
    float s  = g_colsum[j];
    float q  = g_colsq[j];
    float mu  = s / (float)N_NODES;
    float var = q / (float)N_NODES - mu * mu;
    float a = gamma[j] * rsqrtf(var + BN_EPS);
    float b = beta[j] - mu * a;
    g_affa[j] = a;
    g_affb[j] = b;
    g_colsum[j] = 0.f;
    g_colsq [j] = 0.f;
}

// ---------------- pooling fused with FC: pool[g] += affine(h[i]) . fc_w ----
__global__ void pool_kernel(const float* __restrict__ h,
                            const int* __restrict__ batch,
                            const float* __restrict__ fcw) {
    int gt   = blockIdx.x * blockDim.x + threadIdx.x;
    int node = gt >> 5;
    int lane = gt & 31;
    if (node >= N_NODES) return;
    float4 v = ((const float4*)h)[node * 32 + lane];
    float4 a = ((const float4*)g_affa)[lane];
    float4 b = ((const float4*)g_affb)[lane];
    float4 w = ((const float4*)fcw)[lane];
    float d = fmaf(v.x, a.x, b.x) * w.x
            + fmaf(v.y, a.y, b.y) * w.y
            + fmaf(v.z, a.z, b.z) * w.z
            + fmaf(v.w, a.w, b.w) * w.w;
#pragma unroll
    for (int off = 16; off; off >>= 1)
        d += __shfl_down_sync(0xffffffff, d, off);
    if (lane == 0) atomicAdd(&g_pool[batch[node]], d);
}

__global__ void out_kernel(const float* __restrict__ fcb, float* __restrict__ out) {
    int g = threadIdx.x;
    if (g < NGRAPHS) out[g] = 1.0f / (1.0f + expf(-(g_pool[g] + fcb[0])));
}

// ---------------- host launcher (graph-capturable) -------------------------
extern "C" void kernel_launch(void* const* d_in, const int* in_sizes, int n_in,
                              void* d_out, int out_size) {
    const float* x        = (const float*)d_in[0];
    const int*   ei       = (const int*)d_in[1];      // int32 per harness dtypes
    /* d_in[2] edge_attr: unused by reference */
    const int*   batch    = (const int*)d_in[3];
    const float* lin_l_w  = (const float*)d_in[4];
    const float* lin_l_b  = (const float*)d_in[5];
    const float* lin_r_w  = (const float*)d_in[6];
    const float* bn_gamma = (const float*)d_in[7];
    const float* bn_beta  = (const float*)d_in[8];
    const float* fc_w     = (const float*)d_in[9];
    const float* fc_b     = (const float*)d_in[10];
    float*       out      = (float*)d_out;

    void *p_agg, *p_deg, *p_b0, *p_b1;
    cudaGetSymbolAddress(&p_agg, g_agg);
    cudaGetSymbolAddress(&p_deg, g_deg);
    cudaGetSymbolAddress(&p_b0,  g_buf0);
    cudaGetSymbolAddress(&p_b1,  g_buf1);
    float* bufs[2] = { (float*)p_b0, (float*)p_b1 };

    cudaMemsetAsync(p_deg, 0, N_NODES * sizeof(float));
    deg_kernel<<<(N_EDGES + 255) / 256, 256>>>(ei);
    init_kernel<<<(N_NODES + 255) / 256, 256>>>();

    const float* hprev = x;
    for (int l = 0; l < NLAYERS; ++l) {
        float* yout = bufs[l & 1];
        cudaMemsetAsync(p_agg, 0, (size_t)N_NODES * HDIM * sizeof(float));
        scatter_kernel<<<(N_EDGES * 32) / 256, 256>>>(hprev, ei);
        gemm_kernel<<<(N_NODES + 63) / 64, 256>>>(
            hprev,
            lin_l_w + (size_t)l * HDIM * HDIM,
            lin_r_w + (size_t)l * HDIM * HDIM,
            lin_l_b + (size_t)l * HDIM,
            yout);
        finalize_kernel<<<1, HDIM>>>(bn_gamma + (size_t)l * HDIM,
                                     bn_beta  + (size_t)l * HDIM);
        hprev = yout;
    }
    pool_kernel<<<(N_NODES * 32 + 255) / 256, 256>>>(hprev, batch, fc_w);
    out_kernel<<<1, NGRAPHS>>>(fc_b, out);
}

// round 3
// speedup vs baseline: 1.4779x; 1.4779x over previous
#include <cuda_runtime.h>
#include <cuda_bf16.h>
#include <math.h>

#define N_NODES 50000
#define N_EDGES 800000
#define HDIM    128
#define NLAYERS 3
#define NGRAPHS 64
#define BN_EPS  1e-5f
#define SCAN_B  1024
#define NSCAN   ((N_NODES + SCAN_B - 1) / SCAN_B)

typedef unsigned long long ull;

// ---------------- scratch (device globals) ----------------------------------
__device__ __align__(16) float g_agg [N_NODES * HDIM];
__device__ __align__(16) float g_buf0[N_NODES * HDIM];
__device__ __align__(16) float g_buf1[N_NODES * HDIM];
__device__ int   g_cnt     [N_NODES];
__device__ int   g_rowstart[N_NODES];
__device__ int   g_cursor  [N_NODES];
__device__ int   g_csr     [N_EDGES];
__device__ int   g_bsum    [NSCAN];
__device__ float g_invdeg  [N_NODES];
__device__ __align__(16) float g_affa[HDIM];
__device__ __align__(16) float g_affb[HDIM];
__device__ __align__(16) float g_wr_eff [HDIM * HDIM];
__device__ float g_bias_eff[HDIM];
__device__ float g_colsum[HDIM];
__device__ float g_colsq [HDIM];
__device__ float g_pool[NGRAPHS];

// ---------------- f32x2 helpers ---------------------------------------------
__device__ __forceinline__ ull fma2(ull a, ull b, ull c) {
    ull d;
    asm("fma.rn.f32x2 %0, %1, %2, %3;" : "=l"(d) : "l"(a), "l"(b), "l"(c));
    return d;
}
__device__ __forceinline__ ull dup2(float x) {
    ull d;
    asm("mov.b64 %0, {%1, %1};" : "=l"(d) : "f"(x));
    return d;
}

// ---------------- CSR build --------------------------------------------------
__global__ void count_kernel(const int* __restrict__ ei) {
    int e = blockIdx.x * blockDim.x + threadIdx.x;
    if (e < N_EDGES) atomicAdd(&g_cnt[ei[N_EDGES + e]], 1);
}

__global__ void scan1_kernel() {
    __shared__ int sh[SCAN_B];
    int i = blockIdx.x * SCAN_B + threadIdx.x;
    int v = (i < N_NODES) ? g_cnt[i] : 0;
    sh[threadIdx.x] = v;
    __syncthreads();
    for (int off = 1; off < SCAN_B; off <<= 1) {
        int t = (threadIdx.x >= off) ? sh[threadIdx.x - off] : 0;
        __syncthreads();
        sh[threadIdx.x] += t;
        __syncthreads();
    }
    if (i < N_NODES) g_rowstart[i] = sh[threadIdx.x] - v;  // exclusive
    if (threadIdx.x == SCAN_B - 1) g_bsum[blockIdx.x] = sh[SCAN_B - 1];
}

__global__ void scan2_kernel() {
    if (threadIdx.x == 0) {
        int run = 0;
        for (int b = 0; b < NSCAN; ++b) {
            int v = g_bsum[b];
            g_bsum[b] = run;
            run += v;
        }
    }
}

__global__ void scan3_kernel() {
    int i = blockIdx.x * blockDim.x + threadIdx.x;
    if (i < N_NODES) {
        int rs = g_rowstart[i] + g_bsum[i / SCAN_B];
        g_rowstart[i] = rs;
        g_cursor[i]   = rs;
        g_invdeg[i]   = 1.0f / fmaxf((float)g_cnt[i], 1.0f);
    }
}

__global__ void fill_kernel(const int* __restrict__ ei) {
    int e = blockIdx.x * blockDim.x + threadIdx.x;
    if (e < N_EDGES) {
        int dst = ei[N_EDGES + e];
        int pos = atomicAdd(&g_cursor[dst], 1);
        g_csr[pos] = ei[e];
    }
}

// affa/affb identity, zero stats/pool
__global__ void init_kernel() {
    int i = blockIdx.x * blockDim.x + threadIdx.x;
    if (i < HDIM) {
        g_affa[i] = 1.0f; g_affb[i] = 0.0f;
        g_colsum[i] = 0.0f; g_colsq[i] = 0.0f;
    }
    if (i < NGRAPHS) g_pool[i] = 0.0f;
}

// ---------------- gather-aggregate (no atomics) -----------------------------
// one warp per dst node; lane owns a float4 slice of the 128-dim feature.
// agg[n] = affa * (sum_{src} h[src]) * invdeg + affb * (deg>0)
__global__ void __launch_bounds__(256)
aggregate_kernel(const float* __restrict__ h) {
    __shared__ int sidx[8][32];
    int gt   = blockIdx.x * blockDim.x + threadIdx.x;
    int node = gt >> 5;
    int lane = gt & 31;
    int w    = threadIdx.x >> 5;
    if (node >= N_NODES) return;

    int base = g_rowstart[node];
    int deg  = g_cnt[node];
    const float4* h4 = (const float4*)h;

    float4 acc = make_float4(0.f, 0.f, 0.f, 0.f);
    for (int c = 0; c < deg; c += 32) {
        int s = (c + lane < deg) ? g_csr[base + c + lane] : 0;
        sidx[w][lane] = s;
        __syncwarp();
        int m = min(32, deg - c);
#pragma unroll 4
        for (int j = 0; j < m; ++j) {
            float4 v = h4[sidx[w][j] * 32 + lane];
            acc.x += v.x; acc.y += v.y; acc.z += v.z; acc.w += v.w;
        }
        __syncwarp();
    }
    float id = g_invdeg[node];
    float bs = (deg > 0) ? 1.0f : 0.0f;
    float4 a = ((const float4*)g_affa)[lane];
    float4 b = ((const float4*)g_affb)[lane];
    float4 r;
    r.x = fmaf(acc.x * id, a.x, b.x * bs);
    r.y = fmaf(acc.y * id, a.y, b.y * bs);
    r.z = fmaf(acc.z * id, a.z, b.z * bs);
    r.w = fmaf(acc.w * id, a.w, b.w * bs);
    ((float4*)g_agg)[node * 32 + lane] = r;
}

// ---------------- fold BN affine into Wr + bias ------------------------------
// wr_eff[j,k] = Wr[j,k]*affa[k];  bias_eff[j] = bias[j] + sum_k affb[k]*Wr[j,k]
__global__ void prep_kernel(const float* __restrict__ Wr,
                            const float* __restrict__ bias) {
    __shared__ float red[4];
    int j = blockIdx.x;
    int k = threadIdx.x;
    float w = Wr[j * HDIM + k];
    float a = g_affa[k], b = g_affb[k];
    g_wr_eff[j * HDIM + k] = w * a;
    float p = w * b;
#pragma unroll
    for (int off = 16; off; off >>= 1) p += __shfl_down_sync(0xffffffff, p, off);
    if ((k & 31) == 0) red[k >> 5] = p;
    __syncthreads();
    if (k == 0) g_bias_eff[j] = bias[j] + red[0] + red[1] + red[2] + red[3];
}

// ---------------- fused dual GEMM (f32x2) + bias + relu + BN stats -----------
// y[i,:] = relu( agg[i,:] @ Wl^T + hprev[i,:] @ wr_eff^T + bias_eff )
// block: 64 rows x 128 cols, 256 threads, 8x4 outputs/thread as 4 row-pairs.
#define AS_STRIDE 66
__global__ void __launch_bounds__(256)
gemm_kernel(const float* __restrict__ hprev,
            const float* __restrict__ Wl,
            float* __restrict__ yout) {
    __shared__ __align__(16) float As[32 * AS_STRIDE];  // [k][row], row-pairs packed
    __shared__ __align__(16) float Bs[32 * 132];        // [k][col]
    __shared__ float s_cs[HDIM];
    __shared__ float s_sq[HDIM];

    const int tid  = threadIdx.x;
    const int ty   = tid >> 5;       // warp 0..7 -> rows ty*8 .. ty*8+7
    const int tx   = tid & 31;       // cols tx*4 .. tx*4+3
    const int row0 = blockIdx.x * 64;

    ull acc2[4][4];
#pragma unroll
    for (int p = 0; p < 4; ++p)
#pragma unroll
        for (int j = 0; j < 4; ++j) acc2[p][j] = 0ull;

#pragma unroll 1
    for (int t = 0; t < 8; ++t) {
        const int  kk     = t * 32;
        const bool second = (kk >= 128);
        const int  kloc   = second ? kk - 128 : kk;
        const float* A = second ? hprev : g_agg;
        const float* W = second ? g_wr_eff : Wl;

        // --- A tile: 64 rows x 32 k, stored transposed As[k][row] ---
#pragma unroll
        for (int i = 0; i < 2; ++i) {
            int f  = tid + 256 * i;        // 0..511 float4 slots
            int r  = f >> 3;               // 0..63
            int c4 = f & 7;                // k-quad
            int grow = row0 + r;
            float4 v = make_float4(0.f, 0.f, 0.f, 0.f);
            if (grow < N_NODES)
                v = *((const float4*)(A + (size_t)grow * HDIM + kloc + c4 * 4));
            As[(c4 * 4 + 0) * AS_STRIDE + r] = v.x;
            As[(c4 * 4 + 1) * AS_STRIDE + r] = v.y;
            As[(c4 * 4 + 2) * AS_STRIDE + r] = v.z;
            As[(c4 * 4 + 3) * AS_STRIDE + r] = v.w;
        }
        // --- B tile: 32 k x 128 cols ---
#pragma unroll
        for (int i = 0; i < 4; ++i) {
            int f  = tid + 256 * i;        // 0..1023
            int j  = f >> 3;               // col
            int kq = f & 7;
            float4 w = *((const float4*)(W + (size_t)j * HDIM + kloc + kq * 4));
            Bs[(kq * 4 + 0) * 132 + j] = w.x;
            Bs[(kq * 4 + 1) * 132 + j] = w.y;
            Bs[(kq * 4 + 2) * 132 + j] = w.z;
            Bs[(kq * 4 + 3) * 132 + j] = w.w;
        }
        __syncthreads();

#pragma unroll
        for (int k = 0; k < 32; ++k) {
            const ull* ap = (const ull*)(As + k * AS_STRIDE + ty * 8);
            ull a0 = ap[0], a1 = ap[1], a2 = ap[2], a3 = ap[3];
            float4 bv = *((const float4*)(Bs + k * 132 + tx * 4));
            ull b0 = dup2(bv.x), b1 = dup2(bv.y), b2 = dup2(bv.z), b3 = dup2(bv.w);
            acc2[0][0] = fma2(a0, b0, acc2[0][0]);
            acc2[0][1] = fma2(a0, b1, acc2[0][1]);
            acc2[0][2] = fma2(a0, b2, acc2[0][2]);
            acc2[0][3] = fma2(a0, b3, acc2[0][3]);
            acc2[1][0] = fma2(a1, b0, acc2[1][0]);
            acc2[1][1] = fma2(a1, b1, acc2[1][1]);
            acc2[1][2] = fma2(a1, b2, acc2[1][2]);
            acc2[1][3] = fma2(a1, b3, acc2[1][3]);
            acc2[2][0] = fma2(a2, b0, acc2[2][0]);
            acc2[2][1] = fma2(a2, b1, acc2[2][1]);
            acc2[2][2] = fma2(a2, b2, acc2[2][2]);
            acc2[2][3] = fma2(a2, b3, acc2[2][3]);
            acc2[3][0] = fma2(a3, b0, acc2[3][0]);
            acc2[3][1] = fma2(a3, b1, acc2[3][1]);
            acc2[3][2] = fma2(a3, b2, acc2[3][2]);
            acc2[3][3] = fma2(a3, b3, acc2[3][3]);
        }
        __syncthreads();
    }

    // --- epilogue: bias, relu, store, BN stats ---
    const int col = tx * 4;
    float4 bi = *((const float4*)(g_bias_eff + col));
    float cs[4] = {0.f, 0.f, 0.f, 0.f};
    float sq[4] = {0.f, 0.f, 0.f, 0.f};
#pragma unroll
    for (int p = 0; p < 4; ++p) {
        float lo[4], hi[4];
#pragma unroll
        for (int j = 0; j < 4; ++j) {
            lo[j] = __uint_as_float((unsigned)(acc2[p][j] & 0xffffffffull));
            hi[j] = __uint_as_float((unsigned)(acc2[p][j] >> 32));
        }
        int grow = row0 + ty * 8 + 2 * p;
        if (grow < N_NODES) {
            float4 r;
            r.x = fmaxf(lo[0] + bi.x, 0.f);
            r.y = fmaxf(lo[1] + bi.y, 0.f);
            r.z = fmaxf(lo[2] + bi.z, 0.f);
            r.w = fmaxf(lo[3] + bi.w, 0.f);
            *((float4*)(yout + (size_t)grow * HDIM + col)) = r;
            cs[0] += r.x; sq[0] += r.x * r.x;
            cs[1] += r.y; sq[1] += r.y * r.y;
            cs[2] += r.z; sq[2] += r.z * r.z;
            cs[3] += r.w; sq[3] += r.w * r.w;
        }
        if (grow + 1 < N_NODES) {
            float4 r;
            r.x = fmaxf(hi[0] + bi.x, 0.f);
            r.y = fmaxf(hi[1] + bi.y, 0.f);
            r.z = fmaxf(hi[2] + bi.z, 0.f);
            r.w = fmaxf(hi[3] + bi.w, 0.f);
            *((float4*)(yout + (size_t)(grow + 1) * HDIM + col)) = r;
            cs[0] += r.x; sq[0] += r.x * r.x;
            cs[1] += r.y; sq[1] += r.y * r.y;
            cs[2] += r.z; sq[2] += r.z * r.z;
            cs[3] += r.w; sq[3] += r.w * r.w;
        }
    }
    if (tid < HDIM) { s_cs[tid] = 0.f; s_sq[tid] = 0.f; }
    __syncthreads();
#pragma unroll
    for (int j = 0; j < 4; ++j) {
        atomicAdd(&s_cs[col + j], cs[j]);
        atomicAdd(&s_sq[col + j], sq[j]);
    }
    __syncthreads();
    if (tid < HDIM) {
        atomicAdd(&g_colsum[tid], s_cs[tid]);
        atomicAdd(&g_colsq [tid], s_sq[tid]);
    }
}

// ---------------- BN finalize -> affine for next consumer -------------------
__global__ void finalize_kernel(const float* __restrict__ gamma,
                                const float* __restrict__ beta) {
    int j = threadIdx.x;
    if (j >= HDIM) return;
    float s  = g_colsum[j];
    float q  = g_colsq[j];
    float mu  = s / (float)N_NODES;
    float var = q / (float)N_NODES - mu * mu;
    float a = gamma[j] * rsqrtf(var + BN_EPS);
    float b = beta[j] - mu * a;
    g_affa[j] = a;
    g_affb[j] = b;
    g_colsum[j] = 0.f;
    g_colsq [j] = 0.f;
}

// ---------------- pooling fused with FC --------------------------------------
__global__ void pool_kernel(const float* __restrict__ h,
                            const int* __restrict__ batch,
                            const float* __restrict__ fcw) {
    int gt   = blockIdx.x * blockDim.x + threadIdx.x;
    int node = gt >> 5;
    int lane = gt & 31;
    if (node >= N_NODES) return;
    float4 v = ((const float4*)h)[node * 32 + lane];
    float4 a = ((const float4*)g_affa)[lane];
    float4 b = ((const float4*)g_affb)[lane];
    float4 w = ((const float4*)fcw)[lane];
    float d = fmaf(v.x, a.x, b.x) * w.x
            + fmaf(v.y, a.y, b.y) * w.y
            + fmaf(v.z, a.z, b.z) * w.z
            + fmaf(v.w, a.w, b.w) * w.w;
#pragma unroll
    for (int off = 16; off; off >>= 1)
        d += __shfl_down_sync(0xffffffff, d, off);
    if (lane == 0) atomicAdd(&g_pool[batch[node]], d);
}

__global__ void out_kernel(const float* __restrict__ fcb, float* __restrict__ out) {
    int g = threadIdx.x;
    if (g < NGRAPHS) out[g] = 1.0f / (1.0f + expf(-(g_pool[g] + fcb[0])));
}

// ---------------- host launcher (graph-capturable) --------------------------
extern "C" void kernel_launch(void* const* d_in, const int* in_sizes, int n_in,
                              void* d_out, int out_size) {
    const float* x        = (const float*)d_in[0];
    const int*   ei       = (const int*)d_in[1];
    /* d_in[2] edge_attr unused */
    const int*   batch    = (const int*)d_in[3];
    const float* lin_l_w  = (const float*)d_in[4];
    const float* lin_l_b  = (const float*)d_in[5];
    const float* lin_r_w  = (const float*)d_in[6];
    const float* bn_gamma = (const float*)d_in[7];
    const float* bn_beta  = (const float*)d_in[8];
    const float* fc_w     = (const float*)d_in[9];
    const float* fc_b     = (const float*)d_in[10];
    float*       out      = (float*)d_out;

    void *p_cnt, *p_b0, *p_b1;
    cudaGetSymbolAddress(&p_cnt, g_cnt);
    cudaGetSymbolAddress(&p_b0,  g_buf0);
    cudaGetSymbolAddress(&p_b1,  g_buf1);
    float* bufs[2] = { (float*)p_b0, (float*)p_b1 };

    // CSR build (once per launch)
    cudaMemsetAsync(p_cnt, 0, N_NODES * sizeof(int));
    count_kernel<<<(N_EDGES + 255) / 256, 256>>>(ei);
    scan1_kernel<<<NSCAN, SCAN_B>>>();
    scan2_kernel<<<1, 32>>>();
    scan3_kernel<<<(N_NODES + 255) / 256, 256>>>();
    fill_kernel<<<(N_EDGES + 255) / 256, 256>>>(ei);
    init_kernel<<<1, 256>>>();

    const float* hprev = x;
    for (int l = 0; l < NLAYERS; ++l) {
        float* yout = bufs[l & 1];
        aggregate_kernel<<<(N_NODES * 32 + 255) / 256, 256>>>(hprev);
        prep_kernel<<<HDIM, HDIM>>>(lin_r_w + (size_t)l * HDIM * HDIM,
                                    lin_l_b + (size_t)l * HDIM);
        gemm_kernel<<<(N_NODES + 63) / 64, 256>>>(
            hprev,
            lin_l_w + (size_t)l * HDIM * HDIM,
            yout);
        finalize_kernel<<<1, HDIM>>>(bn_gamma + (size_t)l * HDIM,
                                     bn_beta  + (size_t)l * HDIM);
        hprev = yout;
    }
    pool_kernel<<<(N_NODES * 32 + 255) / 256, 256>>>(hprev, batch, fc_w);
    out_kernel<<<1, NGRAPHS>>>(fc_b, out);
}